// round 1
// baseline (speedup 1.0000x reference)
#include <cuda_runtime.h>

#define DOUT 128
#define NCAP 50048

// Scratch (device globals — allocation-free rule)
__device__ float g_h[(size_t)NCAP * DOUT];   // ~25.6 MB, fits in L2
__device__ float g_sdst[NCAP];
__device__ float g_ssrc[NCAP];

// ---------------------------------------------------------------------------
// Kernel 1: h = x @ W + b  and  s_dst = h·a_w[:128], s_src = h·a_w[128:]
// Block: 256 threads computing a 64-row x 128-col tile. W fully in smem.
// ---------------------------------------------------------------------------
__global__ void __launch_bounds__(256, 2)
gat_gemm_kernel(const float* __restrict__ x, const float* __restrict__ W,
                const float* __restrict__ b, const float* __restrict__ aw,
                int N) {
    extern __shared__ float smem[];
    float* sW = smem;                  // [128][128] = 64 KB
    float* sx = smem + 128 * 128;      // [64][128]  = 32 KB (row-major)

    const int tid = threadIdx.x;
    const int tx = tid & 31;           // lane: covers cols 4*tx..4*tx+3
    const int ty = tid >> 5;           // warp: covers rows 8*ty..8*ty+7
    const int row0 = blockIdx.x * 64;

    // Load W (128x128) into smem, coalesced float4
    {
        const float4* W4 = (const float4*)W;
        float4* sW4 = (float4*)sW;
#pragma unroll
        for (int i = 0; i < 16; i++)
            sW4[tid + i * 256] = W4[tid + i * 256];
    }
    // Load x tile (64x128) into smem, coalesced float4, zero-padded past N
    {
        float4* sx4 = (float4*)sx;
#pragma unroll
        for (int i = 0; i < 8; i++) {
            int j = tid + i * 256;         // 0..2047 float4s
            int row = j >> 5;              // 0..63
            int kg = j & 31;               // float4 index within row
            float4 v = make_float4(0.f, 0.f, 0.f, 0.f);
            int gr = row0 + row;
            if (gr < N) v = *(const float4*)&x[(size_t)gr * 128 + kg * 4];
            sx4[row * 32 + kg] = v;
        }
    }
    __syncthreads();

    float acc[8][4];
#pragma unroll
    for (int r = 0; r < 8; r++)
#pragma unroll
        for (int c = 0; c < 4; c++) acc[r][c] = 0.f;

#pragma unroll 2
    for (int k = 0; k < 128; k += 4) {
        float4 wr0 = *(const float4*)&sW[(k + 0) * 128 + tx * 4];
        float4 wr1 = *(const float4*)&sW[(k + 1) * 128 + tx * 4];
        float4 wr2 = *(const float4*)&sW[(k + 2) * 128 + tx * 4];
        float4 wr3 = *(const float4*)&sW[(k + 3) * 128 + tx * 4];
#pragma unroll
        for (int r = 0; r < 8; r++) {
            float4 xv = *(const float4*)&sx[(ty * 8 + r) * 128 + k]; // broadcast
            acc[r][0] += xv.x * wr0.x + xv.y * wr1.x + xv.z * wr2.x + xv.w * wr3.x;
            acc[r][1] += xv.x * wr0.y + xv.y * wr1.y + xv.z * wr2.y + xv.w * wr3.y;
            acc[r][2] += xv.x * wr0.z + xv.y * wr1.z + xv.z * wr2.z + xv.w * wr3.z;
            acc[r][3] += xv.x * wr0.w + xv.y * wr1.w + xv.z * wr2.w + xv.w * wr3.w;
        }
    }

    // Epilogue: +bias, write h, fused s_dst / s_src partial dot + warp reduce
    float4 bv = *(const float4*)&b[tx * 4];
    float awd0 = aw[tx * 4 + 0], awd1 = aw[tx * 4 + 1];
    float awd2 = aw[tx * 4 + 2], awd3 = aw[tx * 4 + 3];
    float aws0 = aw[128 + tx * 4 + 0], aws1 = aw[128 + tx * 4 + 1];
    float aws2 = aw[128 + tx * 4 + 2], aws3 = aw[128 + tx * 4 + 3];

    float pd[8], ps[8];
#pragma unroll
    for (int r = 0; r < 8; r++) {
        float4 h;
        h.x = acc[r][0] + bv.x;
        h.y = acc[r][1] + bv.y;
        h.z = acc[r][2] + bv.z;
        h.w = acc[r][3] + bv.w;
        int gr = row0 + ty * 8 + r;
        if (gr < N)
            *(float4*)&g_h[(size_t)gr * 128 + tx * 4] = h;
        pd[r] = h.x * awd0 + h.y * awd1 + h.z * awd2 + h.w * awd3;
        ps[r] = h.x * aws0 + h.y * aws1 + h.z * aws2 + h.w * aws3;
    }
#pragma unroll
    for (int off = 16; off; off >>= 1) {
#pragma unroll
        for (int r = 0; r < 8; r++) {
            pd[r] += __shfl_xor_sync(0xffffffffu, pd[r], off);
            ps[r] += __shfl_xor_sync(0xffffffffu, ps[r], off);
        }
    }
    if (tx == 0) {
#pragma unroll
        for (int r = 0; r < 8; r++) {
            int gr = row0 + ty * 8 + r;
            if (gr < N) {
                g_sdst[gr] = pd[r];
                g_ssrc[gr] = ps[r];
            }
        }
    }
}

// ---------------------------------------------------------------------------
// Kernel 2: per-destination-node softmax + aggregation.
// edge_dst is SORTED -> one warp per node, inline binary search for segment
// bounds, no atomics, no per-edge storage.
// out[n] = (1/sum_e w_e) * sum_e w_e * h[src_e],  w_e = exp(leaky(l_e) - m_n)
// ---------------------------------------------------------------------------
__global__ void __launch_bounds__(256)
gat_agg_kernel(const int* __restrict__ esrc, const int* __restrict__ edst,
               const float* __restrict__ abp, float* __restrict__ out,
               int N, int E) {
    const int gw = (int)((blockIdx.x * blockDim.x + threadIdx.x) >> 5);
    const int lane = threadIdx.x & 31;
    if (gw >= N) return;
    const int n = gw;
    const float ab = __ldg(abp);

    // lower_bound(edst, n) on lane 0, lower_bound(edst, n+1) on lanes>=1
    int target = n + (lane != 0);
    int lo = 0, len = E;
    while (len > 0) {
        int half = len >> 1;
        int mid = lo + half;
        if (__ldg(&edst[mid]) < target) { lo = mid + 1; len -= half + 1; }
        else len = half;
    }
    const int start = __shfl_sync(0xffffffffu, lo, 0);
    const int end   = __shfl_sync(0xffffffffu, lo, 1);
    const int deg = end - start;

    const float sdn = g_sdst[n];
    float4 acc = make_float4(0.f, 0.f, 0.f, 0.f);
    float denom = 0.f;

    if (deg <= 32) {
        // Fast path (~99.9% of nodes at mean degree 16): single chunk,
        // logits computed once and kept in registers.
        int e = start + lane;
        int src = 0;
        float l = -1e30f;
        if (e < end) {
            src = __ldg(&esrc[e]);
            l = sdn + g_ssrc[src] + ab;
            l = (l >= 0.f) ? l : 0.01f * l;
        }
        float m = l;
#pragma unroll
        for (int off = 16; off; off >>= 1)
            m = fmaxf(m, __shfl_xor_sync(0xffffffffu, m, off));
        float w = (e < end) ? __expf(l - m) : 0.f;
        denom = w;
#pragma unroll 4
        for (int j = 0; j < deg; j++) {
            float wj = __shfl_sync(0xffffffffu, w, j);
            int sj = __shfl_sync(0xffffffffu, src, j);
            float4 hv = *(const float4*)&g_h[(size_t)sj * 128 + lane * 4];
            acc.x += wj * hv.x;
            acc.y += wj * hv.y;
            acc.z += wj * hv.z;
            acc.w += wj * hv.w;
        }
    } else {
        // General path: pass 1 max, pass 2 accumulate.
        float m = -1e30f;
        for (int e = start + lane; e < end; e += 32) {
            int src = __ldg(&esrc[e]);
            float l = sdn + g_ssrc[src] + ab;
            l = (l >= 0.f) ? l : 0.01f * l;
            m = fmaxf(m, l);
        }
#pragma unroll
        for (int off = 16; off; off >>= 1)
            m = fmaxf(m, __shfl_xor_sync(0xffffffffu, m, off));

        for (int base = start; base < end; base += 32) {
            int e = base + lane;
            int src = 0;
            float w = 0.f;
            if (e < end) {
                src = __ldg(&esrc[e]);
                float l = sdn + g_ssrc[src] + ab;
                l = (l >= 0.f) ? l : 0.01f * l;
                w = __expf(l - m);
                denom += w;
            }
            int cnt = min(32, end - base);
#pragma unroll 4
            for (int j = 0; j < cnt; j++) {
                float wj = __shfl_sync(0xffffffffu, w, j);
                int sj = __shfl_sync(0xffffffffu, src, j);
                float4 hv = *(const float4*)&g_h[(size_t)sj * 128 + lane * 4];
                acc.x += wj * hv.x;
                acc.y += wj * hv.y;
                acc.z += wj * hv.z;
                acc.w += wj * hv.w;
            }
        }
    }

#pragma unroll
    for (int off = 16; off; off >>= 1)
        denom += __shfl_xor_sync(0xffffffffu, denom, off);
    float inv = (denom > 0.f) ? (1.f / denom) : 0.f;
    acc.x *= inv; acc.y *= inv; acc.z *= inv; acc.w *= inv;
    *(float4*)&out[(size_t)n * 128 + lane * 4] = acc;
}

// ---------------------------------------------------------------------------
extern "C" void kernel_launch(void* const* d_in, const int* in_sizes, int n_in,
                              void* d_out, int out_size) {
    const float* x    = (const float*)d_in[0];
    const int*   esrc = (const int*)d_in[1];
    const int*   edst = (const int*)d_in[2];
    const float* W    = (const float*)d_in[3];
    const float* b    = (const float*)d_in[4];
    const float* aw   = (const float*)d_in[5];
    const float* ab   = (const float*)d_in[6];
    float* out = (float*)d_out;

    const int N = in_sizes[0] / DOUT;
    const int E = in_sizes[1];

    const int smem_bytes = (128 * 128 + 64 * 128) * (int)sizeof(float); // 96 KB
    cudaFuncSetAttribute(gat_gemm_kernel,
                         cudaFuncAttributeMaxDynamicSharedMemorySize, smem_bytes);

    int gemm_blocks = (N + 63) / 64;
    gat_gemm_kernel<<<gemm_blocks, 256, smem_bytes>>>(x, W, b, aw, N);

    int agg_blocks = (N + 7) / 8;   // 8 warps/block, 1 warp per node
    gat_agg_kernel<<<agg_blocks, 256>>>(esrc, edst, ab, out, N, E);
}

// round 2
// speedup vs baseline: 1.1278x; 1.1278x over previous
#include <cuda_runtime.h>

#define DOUT 128
#define NCAP 50048

// Scratch (device globals — allocation-free rule)
__device__ float g_h[(size_t)NCAP * DOUT];   // ~25.6 MB, fits in L2
__device__ float g_sdst[NCAP];
__device__ float g_ssrc[NCAP];
__device__ int   g_seg[NCAP + 1];            // segment start offsets

// ---------------------------------------------------------------------------
// Kernel 0a: init seg offsets to E (covers trailing / gap nodes)
// ---------------------------------------------------------------------------
__global__ void seg_init_kernel(int* __restrict__ seg, int N, int E) {
    int i = blockIdx.x * blockDim.x + threadIdx.x;
    if (i <= N) seg[i] = E;
}

// ---------------------------------------------------------------------------
// Kernel 0b: edge_dst is sorted -> write boundary offsets.
// seg[n] = first edge index with edst >= n.
// ---------------------------------------------------------------------------
__global__ void seg_build_kernel(const int* __restrict__ edst,
                                 int* __restrict__ seg, int E) {
    int e = blockIdx.x * blockDim.x + threadIdx.x;
    if (e >= E) return;
    int d = __ldg(&edst[e]);
    int dprev = (e == 0) ? -1 : __ldg(&edst[e - 1]);
    // covers gap nodes too (deg-0 nodes get start == end)
    for (int n = dprev + 1; n <= d; n++) seg[n] = e;
}

// ---------------------------------------------------------------------------
// Kernel 1: h = x @ W + b  and  s_dst = h·a_w[:128], s_src = h·a_w[128:]
// (unchanged — measured at the SIMT FFMA roofline)
// ---------------------------------------------------------------------------
__global__ void __launch_bounds__(256, 2)
gat_gemm_kernel(const float* __restrict__ x, const float* __restrict__ W,
                const float* __restrict__ b, const float* __restrict__ aw,
                int N) {
    extern __shared__ float smem[];
    float* sW = smem;                  // [128][128] = 64 KB
    float* sx = smem + 128 * 128;      // [64][128]  = 32 KB

    const int tid = threadIdx.x;
    const int tx = tid & 31;
    const int ty = tid >> 5;
    const int row0 = blockIdx.x * 64;

    {
        const float4* W4 = (const float4*)W;
        float4* sW4 = (float4*)sW;
#pragma unroll
        for (int i = 0; i < 16; i++)
            sW4[tid + i * 256] = W4[tid + i * 256];
    }
    {
        float4* sx4 = (float4*)sx;
#pragma unroll
        for (int i = 0; i < 8; i++) {
            int j = tid + i * 256;
            int row = j >> 5;
            int kg = j & 31;
            float4 v = make_float4(0.f, 0.f, 0.f, 0.f);
            int gr = row0 + row;
            if (gr < N) v = *(const float4*)&x[(size_t)gr * 128 + kg * 4];
            sx4[row * 32 + kg] = v;
        }
    }
    __syncthreads();

    float acc[8][4];
#pragma unroll
    for (int r = 0; r < 8; r++)
#pragma unroll
        for (int c = 0; c < 4; c++) acc[r][c] = 0.f;

#pragma unroll 2
    for (int k = 0; k < 128; k += 4) {
        float4 wr0 = *(const float4*)&sW[(k + 0) * 128 + tx * 4];
        float4 wr1 = *(const float4*)&sW[(k + 1) * 128 + tx * 4];
        float4 wr2 = *(const float4*)&sW[(k + 2) * 128 + tx * 4];
        float4 wr3 = *(const float4*)&sW[(k + 3) * 128 + tx * 4];
#pragma unroll
        for (int r = 0; r < 8; r++) {
            float4 xv = *(const float4*)&sx[(ty * 8 + r) * 128 + k];
            acc[r][0] += xv.x * wr0.x + xv.y * wr1.x + xv.z * wr2.x + xv.w * wr3.x;
            acc[r][1] += xv.x * wr0.y + xv.y * wr1.y + xv.z * wr2.y + xv.w * wr3.y;
            acc[r][2] += xv.x * wr0.z + xv.y * wr1.z + xv.z * wr2.z + xv.w * wr3.z;
            acc[r][3] += xv.x * wr0.w + xv.y * wr1.w + xv.z * wr2.w + xv.w * wr3.w;
        }
    }

    float4 bv = *(const float4*)&b[tx * 4];
    float awd0 = aw[tx * 4 + 0], awd1 = aw[tx * 4 + 1];
    float awd2 = aw[tx * 4 + 2], awd3 = aw[tx * 4 + 3];
    float aws0 = aw[128 + tx * 4 + 0], aws1 = aw[128 + tx * 4 + 1];
    float aws2 = aw[128 + tx * 4 + 2], aws3 = aw[128 + tx * 4 + 3];

    float pd[8], ps[8];
#pragma unroll
    for (int r = 0; r < 8; r++) {
        float4 h;
        h.x = acc[r][0] + bv.x;
        h.y = acc[r][1] + bv.y;
        h.z = acc[r][2] + bv.z;
        h.w = acc[r][3] + bv.w;
        int gr = row0 + ty * 8 + r;
        if (gr < N)
            *(float4*)&g_h[(size_t)gr * 128 + tx * 4] = h;
        pd[r] = h.x * awd0 + h.y * awd1 + h.z * awd2 + h.w * awd3;
        ps[r] = h.x * aws0 + h.y * aws1 + h.z * aws2 + h.w * aws3;
    }
#pragma unroll
    for (int off = 16; off; off >>= 1) {
#pragma unroll
        for (int r = 0; r < 8; r++) {
            pd[r] += __shfl_xor_sync(0xffffffffu, pd[r], off);
            ps[r] += __shfl_xor_sync(0xffffffffu, ps[r], off);
        }
    }
    if (tx == 0) {
#pragma unroll
        for (int r = 0; r < 8; r++) {
            int gr = row0 + ty * 8 + r;
            if (gr < N) {
                g_sdst[gr] = pd[r];
                g_ssrc[gr] = ps[r];
            }
        }
    }
}

// ---------------------------------------------------------------------------
// Kernel 2: per-destination softmax + aggregation. Warp per node.
// Segment bounds read from g_seg (no binary search). Per-warp smem buffer
// of packed (w, src) replaces SHFL broadcasts in the gather loop.
// ---------------------------------------------------------------------------
__global__ void __launch_bounds__(256)
gat_agg_kernel(const int* __restrict__ esrc,
               const float* __restrict__ abp, float* __restrict__ out,
               int N) {
    __shared__ float2 wbuf_all[8][32];   // 8 warps * 32 edges * (w, src)

    const int warp = threadIdx.x >> 5;
    const int lane = threadIdx.x & 31;
    const int n = blockIdx.x * 8 + warp;
    if (n >= N) return;
    const float ab = __ldg(abp);

    const int start = __ldg(&g_seg[n]);
    const int end   = __ldg(&g_seg[n + 1]);
    const int deg = end - start;

    const float sdn = __ldg(&g_sdst[n]);
    float2* wbuf = wbuf_all[warp];
    float4 acc = make_float4(0.f, 0.f, 0.f, 0.f);
    float denom = 0.f;

    if (deg <= 32) {
        // Fast path (~all nodes at mean degree 16)
        int e = start + lane;
        int src = 0;
        float l = -1e30f;
        if (e < end) {
            src = __ldg(&esrc[e]);
            l = sdn + __ldg(&g_ssrc[src]) + ab;
            l = (l >= 0.f) ? l : 0.01f * l;
        }
        float m = l;
#pragma unroll
        for (int off = 16; off; off >>= 1)
            m = fmaxf(m, __shfl_xor_sync(0xffffffffu, m, off));
        float w = (e < end) ? __expf(l - m) : 0.f;
        denom = w;
        wbuf[lane] = make_float2(w, __int_as_float(src));
        __syncwarp();
#pragma unroll 4
        for (int j = 0; j < deg; j++) {
            float2 p = wbuf[j];                    // broadcast LDS.64
            int sj = __float_as_int(p.y);
            float4 hv = *(const float4*)&g_h[(size_t)sj * 128 + lane * 4];
            acc.x += p.x * hv.x;
            acc.y += p.x * hv.y;
            acc.z += p.x * hv.z;
            acc.w += p.x * hv.w;
        }
    } else {
        // General path: pass 1 max, pass 2 chunked accumulate
        float m = -1e30f;
        for (int e = start + lane; e < end; e += 32) {
            int src = __ldg(&esrc[e]);
            float l = sdn + __ldg(&g_ssrc[src]) + ab;
            l = (l >= 0.f) ? l : 0.01f * l;
            m = fmaxf(m, l);
        }
#pragma unroll
        for (int off = 16; off; off >>= 1)
            m = fmaxf(m, __shfl_xor_sync(0xffffffffu, m, off));

        for (int base = start; base < end; base += 32) {
            int e = base + lane;
            int src = 0;
            float w = 0.f;
            if (e < end) {
                src = __ldg(&esrc[e]);
                float l = sdn + __ldg(&g_ssrc[src]) + ab;
                l = (l >= 0.f) ? l : 0.01f * l;
                w = __expf(l - m);
                denom += w;
            }
            __syncwarp();
            wbuf[lane] = make_float2(w, __int_as_float(src));
            __syncwarp();
            int cnt = min(32, end - base);
#pragma unroll 4
            for (int j = 0; j < cnt; j++) {
                float2 p = wbuf[j];
                int sj = __float_as_int(p.y);
                float4 hv = *(const float4*)&g_h[(size_t)sj * 128 + lane * 4];
                acc.x += p.x * hv.x;
                acc.y += p.x * hv.y;
                acc.z += p.x * hv.z;
                acc.w += p.x * hv.w;
            }
        }
    }

#pragma unroll
    for (int off = 16; off; off >>= 1)
        denom += __shfl_xor_sync(0xffffffffu, denom, off);
    float inv = (denom > 0.f) ? (1.f / denom) : 0.f;
    acc.x *= inv; acc.y *= inv; acc.z *= inv; acc.w *= inv;
    *(float4*)&out[(size_t)n * 128 + lane * 4] = acc;
}

// ---------------------------------------------------------------------------
extern "C" void kernel_launch(void* const* d_in, const int* in_sizes, int n_in,
                              void* d_out, int out_size) {
    const float* x    = (const float*)d_in[0];
    const int*   esrc = (const int*)d_in[1];
    const int*   edst = (const int*)d_in[2];
    const float* W    = (const float*)d_in[3];
    const float* b    = (const float*)d_in[4];
    const float* aw   = (const float*)d_in[5];
    const float* ab   = (const float*)d_in[6];
    float* out = (float*)d_out;

    const int N = in_sizes[0] / DOUT;
    const int E = in_sizes[1];

    int* seg;
    cudaGetSymbolAddress((void**)&seg, g_seg);

    // Segment offsets (tiny)
    seg_init_kernel<<<(N + 256) / 256, 256>>>(seg, N, E);
    seg_build_kernel<<<(E + 255) / 256, 256>>>(edst, seg, E);

    // GEMM
    const int smem_bytes = (128 * 128 + 64 * 128) * (int)sizeof(float); // 96 KB
    cudaFuncSetAttribute(gat_gemm_kernel,
                         cudaFuncAttributeMaxDynamicSharedMemorySize, smem_bytes);
    int gemm_blocks = (N + 63) / 64;
    gat_gemm_kernel<<<gemm_blocks, 256, smem_bytes>>>(x, W, b, aw, N);

    // Aggregation
    int agg_blocks = (N + 7) / 8;
    gat_agg_kernel<<<agg_blocks, 256>>>(esrc, ab, out, N);
}

// round 4
// speedup vs baseline: 1.4988x; 1.3290x over previous
#include <cuda_runtime.h>
#include <cuda_bf16.h>
#include <cuda_fp16.h>
#include <cstdint>

#define DOUT 128
#define NCAP 50048
#define LDA 136            // padded smem row stride in bf16 elems (272 B)

// Scratch (device globals — allocation-free rule)
__device__ __half   g_hh[(size_t)NCAP * DOUT];   // h in fp16 (12.8 MB, L2-resident)
__device__ float    g_sdst[NCAP];
__device__ float    g_ssrc[NCAP];
__device__ int      g_seg[NCAP + 1];
__device__ __nv_bfloat16 g_wbhi[128 * LDA + 64]; // W^T bf16 hi, padded layout
__device__ __nv_bfloat16 g_wblo[128 * LDA + 64]; // W^T bf16 lo, padded layout

__device__ __forceinline__ uint32_t smem_u32(const void* p) {
    uint32_t a;
    asm("{ .reg .u64 t; cvta.to.shared.u64 t, %1; cvt.u32.u64 %0, t; }" : "=r"(a) : "l"(p));
    return a;
}

__device__ __forceinline__ void ldsm_x4(uint32_t* r, uint32_t addr) {
    asm volatile("ldmatrix.sync.aligned.m8n8.x4.shared.b16 {%0,%1,%2,%3}, [%4];"
                 : "=r"(r[0]), "=r"(r[1]), "=r"(r[2]), "=r"(r[3]) : "r"(addr));
}

__device__ __forceinline__ void mma_bf16(float* c, const uint32_t* a, const uint32_t* b) {
    asm volatile(
        "mma.sync.aligned.m16n8k16.row.col.f32.bf16.bf16.f32 "
        "{%0,%1,%2,%3}, {%4,%5,%6,%7}, {%8,%9}, {%0,%1,%2,%3};"
        : "+f"(c[0]), "+f"(c[1]), "+f"(c[2]), "+f"(c[3])
        : "r"(a[0]), "r"(a[1]), "r"(a[2]), "r"(a[3]), "r"(b[0]), "r"(b[1]));
}

// ---------------------------------------------------------------------------
// Kernel 0a/0b: segment offsets (edge_dst sorted)
// ---------------------------------------------------------------------------
__global__ void seg_init_kernel(int N, int E) {
    int i = blockIdx.x * blockDim.x + threadIdx.x;
    if (i <= N) g_seg[i] = E;
}

__global__ void seg_build_kernel(const int* __restrict__ edst, int E) {
    int e = blockIdx.x * blockDim.x + threadIdx.x;
    if (e >= E) return;
    int d = __ldg(&edst[e]);
    int dprev = (e == 0) ? -1 : __ldg(&edst[e - 1]);
    for (int n = dprev + 1; n <= d; n++) g_seg[n] = e;
}

// ---------------------------------------------------------------------------
// Kernel 0c: W^T split to bf16 hi/lo in padded [n][LDA] layout.
// B[n][k] = W[k][n] (the .col operand of mma is K-contiguous per n-row).
// ---------------------------------------------------------------------------
__global__ void prep_w_kernel(const float* __restrict__ W) {
    int idx = blockIdx.x * blockDim.x + threadIdx.x;
    if (idx >= 128 * 128) return;
    int k = idx >> 7, n = idx & 127;
    float w = W[idx];                         // W[k][n]
    __nv_bfloat16 hi = __float2bfloat16(w);
    __nv_bfloat16 lo = __float2bfloat16(w - __bfloat162float(hi));
    g_wbhi[n * LDA + k] = hi;
    g_wblo[n * LDA + k] = lo;
}

// ---------------------------------------------------------------------------
// Kernel 1: bf16-split tensor GEMM (mma.sync m16n8k16, fp32 accum).
// CTA = 128x128x128. 8 warps, each 32(m) x 64(n). Terms: AhiBhi+AhiBlo+AloBhi.
// Epilogue: +bias, h -> fp16 gmem, exact fp32 s_dst/s_src via quad-shfl +
// cross-warp smem reduction.
// ---------------------------------------------------------------------------
static const uint32_t A_HI = 0;
static const uint32_t A_LO = 34816;
static const uint32_t B_HI = 69632;
static const uint32_t B_LO = 104448;
static const uint32_t SC_AW = 139264;   // 256 floats
static const uint32_t SC_B  = 140288;   // 128 floats
static const uint32_t S_PD  = 140800;   // 2*128 floats
static const uint32_t S_PS  = 141824;   // 2*128 floats
static const uint32_t GEMM_SMEM = 142848;

__global__ void __launch_bounds__(256, 1)
gat_gemm_mma_kernel(const float* __restrict__ x, const float* __restrict__ b,
                    const float* __restrict__ aw, int N) {
    extern __shared__ char smem[];
    const uint32_t sb = smem_u32(smem);
    const int tid = threadIdx.x, wid = tid >> 5, lane = tid & 31;
    const int warp_m = wid >> 1, warp_n = wid & 1;
    const int m0 = warp_m * 32, n0 = warp_n * 64;
    const int row0 = blockIdx.x * 128;

    // scalars
    ((float*)(smem + SC_AW))[tid] = aw[tid];
    if (tid < 128) ((float*)(smem + SC_B))[tid] = b[tid];

    // B tiles: linear copy of prepped padded W^T hi/lo (34816 B each)
    {
        uint4* dhi = (uint4*)(smem + B_HI);
        uint4* dlo = (uint4*)(smem + B_LO);
        const uint4* shi = (const uint4*)g_wbhi;
        const uint4* slo = (const uint4*)g_wblo;
        for (int i = tid; i < 2176; i += 256) {
            dhi[i] = shi[i];
            dlo[i] = slo[i];
        }
    }

    // A tile: coalesced fp32 loads, bf16 hi/lo split, padded stores
#pragma unroll
    for (int i = 0; i < 16; i++) {
        int j = tid + i * 256;            // 0..4095 float4s
        int row = j >> 5;
        int c = (j & 31) * 4;
        float4 v = make_float4(0.f, 0.f, 0.f, 0.f);
        int gr = row0 + row;
        if (gr < N) v = *(const float4*)&x[(size_t)gr * 128 + c];
        __nv_bfloat162 h01 = __floats2bfloat162_rn(v.x, v.y);
        __nv_bfloat162 h23 = __floats2bfloat162_rn(v.z, v.w);
        float l0 = v.x - __bfloat162float(h01.x);
        float l1 = v.y - __bfloat162float(h01.y);
        float l2 = v.z - __bfloat162float(h23.x);
        float l3 = v.w - __bfloat162float(h23.y);
        __nv_bfloat162 lo01 = __floats2bfloat162_rn(l0, l1);
        __nv_bfloat162 lo23 = __floats2bfloat162_rn(l2, l3);
        uint32_t off = (uint32_t)(row * LDA + c) * 2;
        *(uint2*)(smem + A_HI + off) = make_uint2(*(uint32_t*)&h01, *(uint32_t*)&h23);
        *(uint2*)(smem + A_LO + off) = make_uint2(*(uint32_t*)&lo01, *(uint32_t*)&lo23);
    }
    __syncthreads();

    float acc[2][8][4];
#pragma unroll
    for (int mb = 0; mb < 2; mb++)
#pragma unroll
        for (int nb = 0; nb < 8; nb++)
#pragma unroll
            for (int q = 0; q < 4; q++) acc[mb][nb][q] = 0.f;

    const int a_row = lane & 15, a_half = (lane >> 4) * 8;
    const uint32_t aBase[3] = {sb + A_HI, sb + A_HI, sb + A_LO};
    const uint32_t bBase[3] = {sb + B_HI, sb + B_LO, sb + B_HI};

#pragma unroll
    for (int t3 = 0; t3 < 3; t3++) {
        uint32_t ab = aBase[t3], bb = bBase[t3];
#pragma unroll
        for (int ks = 0; ks < 8; ks++) {
            int k0 = ks * 16;
            uint32_t afr[2][4], bfr[8][2];
#pragma unroll
            for (int mb = 0; mb < 2; mb++)
                ldsm_x4(afr[mb],
                        ab + (uint32_t)((m0 + mb * 16 + a_row) * LDA + k0 + a_half) * 2);
#pragma unroll
            for (int p = 0; p < 4; p++) {
                uint32_t r[4];
                ldsm_x4(r, bb + (uint32_t)((n0 + p * 16 + a_row) * LDA + k0 + a_half) * 2);
                bfr[2 * p][0] = r[0]; bfr[2 * p][1] = r[2];
                bfr[2 * p + 1][0] = r[1]; bfr[2 * p + 1][1] = r[3];
            }
#pragma unroll
            for (int mb = 0; mb < 2; mb++)
#pragma unroll
                for (int nb = 0; nb < 8; nb++)
                    mma_bf16(acc[mb][nb], afr[mb], bfr[nb]);
        }
    }

    // Epilogue
    const float* s_awd = (const float*)(smem + SC_AW);
    const float* s_aws = s_awd + 128;
    const float* s_bb  = (const float*)(smem + SC_B);
    float pd4[4] = {0.f, 0.f, 0.f, 0.f};   // q = mb*2 + half
    float ps4[4] = {0.f, 0.f, 0.f, 0.f};

#pragma unroll
    for (int mb = 0; mb < 2; mb++) {
        int r0w = m0 + mb * 16 + (lane >> 2);
        int gr0 = row0 + r0w;
        int gr1 = gr0 + 8;
#pragma unroll
        for (int nb = 0; nb < 8; nb++) {
            int col = n0 + nb * 8 + (lane & 3) * 2;
            float bc0 = s_bb[col], bc1 = s_bb[col + 1];
            float v00 = acc[mb][nb][0] + bc0;
            float v01 = acc[mb][nb][1] + bc1;
            float v10 = acc[mb][nb][2] + bc0;
            float v11 = acc[mb][nb][3] + bc1;
            float ad0 = s_awd[col], ad1 = s_awd[col + 1];
            float as0 = s_aws[col], as1 = s_aws[col + 1];
            pd4[mb * 2 + 0] = fmaf(v00, ad0, fmaf(v01, ad1, pd4[mb * 2 + 0]));
            pd4[mb * 2 + 1] = fmaf(v10, ad0, fmaf(v11, ad1, pd4[mb * 2 + 1]));
            ps4[mb * 2 + 0] = fmaf(v00, as0, fmaf(v01, as1, ps4[mb * 2 + 0]));
            ps4[mb * 2 + 1] = fmaf(v10, as0, fmaf(v11, as1, ps4[mb * 2 + 1]));
            if (gr0 < N) {
                __half2 hp = __floats2half2_rn(v00, v01);
                *(uint32_t*)&g_hh[(size_t)gr0 * 128 + col] = *(uint32_t*)&hp;
            }
            if (gr1 < N) {
                __half2 hp = __floats2half2_rn(v10, v11);
                *(uint32_t*)&g_hh[(size_t)gr1 * 128 + col] = *(uint32_t*)&hp;
            }
        }
    }

    // quad reduce (lanes 4r..4r+3 hold the same rows)
#pragma unroll
    for (int q = 0; q < 4; q++) {
        pd4[q] += __shfl_xor_sync(0xffffffffu, pd4[q], 1);
        pd4[q] += __shfl_xor_sync(0xffffffffu, pd4[q], 2);
        ps4[q] += __shfl_xor_sync(0xffffffffu, ps4[q], 1);
        ps4[q] += __shfl_xor_sync(0xffffffffu, ps4[q], 2);
    }
    float* sPD = (float*)(smem + S_PD);
    float* sPS = (float*)(smem + S_PS);
    if ((lane & 3) == 0) {
#pragma unroll
        for (int q = 0; q < 4; q++) {
            int r = m0 + (q >> 1) * 16 + (q & 1) * 8 + (lane >> 2);
            sPD[warp_n * 128 + r] = pd4[q];
            sPS[warp_n * 128 + r] = ps4[q];
        }
    }
    __syncthreads();
    if (tid < 128) {
        int gr = row0 + tid;
        if (gr < N) {
            g_sdst[gr] = sPD[tid] + sPD[128 + tid];
            g_ssrc[gr] = sPS[tid] + sPS[128 + tid];
        }
    }
}

// ---------------------------------------------------------------------------
// Kernel 2: per-destination softmax + aggregation (h gathered as fp16).
// ---------------------------------------------------------------------------
__global__ void __launch_bounds__(256)
gat_agg_kernel(const int* __restrict__ esrc,
               const float* __restrict__ abp, float* __restrict__ out, int N) {
    __shared__ float2 wbuf_all[8][32];

    const int warp = threadIdx.x >> 5;
    const int lane = threadIdx.x & 31;
    const int n = blockIdx.x * 8 + warp;
    if (n >= N) return;
    const float ab = __ldg(abp);

    const int start = __ldg(&g_seg[n]);
    const int end   = __ldg(&g_seg[n + 1]);
    const int deg = end - start;

    const float sdn = __ldg(&g_sdst[n]);
    float2* wbuf = wbuf_all[warp];
    float4 acc = make_float4(0.f, 0.f, 0.f, 0.f);
    float denom = 0.f;

    if (deg <= 32) {
        int e = start + lane;
        int src = 0;
        float l = -1e30f;
        if (e < end) {
            src = __ldg(&esrc[e]);
            l = sdn + __ldg(&g_ssrc[src]) + ab;
            l = (l >= 0.f) ? l : 0.01f * l;
        }
        float m = l;
#pragma unroll
        for (int off = 16; off; off >>= 1)
            m = fmaxf(m, __shfl_xor_sync(0xffffffffu, m, off));
        float w = (e < end) ? __expf(l - m) : 0.f;
        denom = w;
        wbuf[lane] = make_float2(w, __int_as_float(src));
        __syncwarp();
#pragma unroll 4
        for (int j = 0; j < deg; j++) {
            float2 p = wbuf[j];
            int sj = __float_as_int(p.y);
            uint2 u = *(const uint2*)&g_hh[(size_t)sj * 128 + lane * 4];
            float2 f0 = __half22float2(*(__half2*)&u.x);
            float2 f1 = __half22float2(*(__half2*)&u.y);
            acc.x += p.x * f0.x;
            acc.y += p.x * f0.y;
            acc.z += p.x * f1.x;
            acc.w += p.x * f1.y;
        }
    } else {
        float m = -1e30f;
        for (int e = start + lane; e < end; e += 32) {
            int src = __ldg(&esrc[e]);
            float l = sdn + __ldg(&g_ssrc[src]) + ab;
            l = (l >= 0.f) ? l : 0.01f * l;
            m = fmaxf(m, l);
        }
#pragma unroll
        for (int off = 16; off; off >>= 1)
            m = fmaxf(m, __shfl_xor_sync(0xffffffffu, m, off));

        for (int base = start; base < end; base += 32) {
            int e = base + lane;
            int src = 0;
            float w = 0.f;
            if (e < end) {
                src = __ldg(&esrc[e]);
                float l = sdn + __ldg(&g_ssrc[src]) + ab;
                l = (l >= 0.f) ? l : 0.01f * l;
                w = __expf(l - m);
                denom += w;
            }
            __syncwarp();
            wbuf[lane] = make_float2(w, __int_as_float(src));
            __syncwarp();
            int cnt = min(32, end - base);
#pragma unroll 4
            for (int j = 0; j < cnt; j++) {
                float2 p = wbuf[j];
                int sj = __float_as_int(p.y);
                uint2 u = *(const uint2*)&g_hh[(size_t)sj * 128 + lane * 4];
                float2 f0 = __half22float2(*(__half2*)&u.x);
                float2 f1 = __half22float2(*(__half2*)&u.y);
                acc.x += p.x * f0.x;
                acc.y += p.x * f0.y;
                acc.z += p.x * f1.x;
                acc.w += p.x * f1.y;
            }
        }
    }

#pragma unroll
    for (int off = 16; off; off >>= 1)
        denom += __shfl_xor_sync(0xffffffffu, denom, off);
    float inv = (denom > 0.f) ? (1.f / denom) : 0.f;
    acc.x *= inv; acc.y *= inv; acc.z *= inv; acc.w *= inv;
    *(float4*)&out[(size_t)n * 128 + lane * 4] = acc;
}

// ---------------------------------------------------------------------------
extern "C" void kernel_launch(void* const* d_in, const int* in_sizes, int n_in,
                              void* d_out, int out_size) {
    const float* x    = (const float*)d_in[0];
    const int*   esrc = (const int*)d_in[1];
    const int*   edst = (const int*)d_in[2];
    const float* W    = (const float*)d_in[3];
    const float* b    = (const float*)d_in[4];
    const float* aw   = (const float*)d_in[5];
    const float* ab   = (const float*)d_in[6];
    float* out = (float*)d_out;

    const int N = in_sizes[0] / DOUT;
    const int E = in_sizes[1];

    seg_init_kernel<<<(N + 256) / 256, 256>>>(N, E);
    seg_build_kernel<<<(E + 255) / 256, 256>>>(edst, E);
    prep_w_kernel<<<64, 256>>>(W);

    cudaFuncSetAttribute(gat_gemm_mma_kernel,
                         cudaFuncAttributeMaxDynamicSharedMemorySize, GEMM_SMEM);
    int gemm_blocks = (N + 127) / 128;
    gat_gemm_mma_kernel<<<gemm_blocks, 256, GEMM_SMEM>>>(x, b, aw, N);

    int agg_blocks = (N + 7) / 8;
    gat_agg_kernel<<<agg_blocks, 256>>>(esrc, ab, out, N);
}